// round 1
// baseline (speedup 1.0000x reference)
#include <cuda_runtime.h>
#include <math.h>

// ----------------------------------------------------------------------------
// DecoderLSTMWithAttention — restructured:
//   (1) attention folded: softmax weights are timestep-invariant (score chain is
//       linear; h-dependent part is a per-batch constant -> softmax invariant).
//   (2) input projection Gpre[t] = [x_t, ctx]@W_ih^T + b hoisted out of the scan.
//   (3) sequential part reduced to 27x (h@W_hh^T, split-K two-phase) + pointwise.
//   (4) one big output GEMM H2(3456,512) @ W_out^T(512,30000) + bias.
//   All fp32, using packed fma.rn.f32x2 (Blackwell FFMA2) in the GEMM cores.
// ----------------------------------------------------------------------------

#define Bb 128
#define Hh 512
#define Ss 80
#define Tt 27
#define Vv 30000

// scratch (device globals: no allocations allowed)
__device__ float g_v0[512];
__device__ float g_v1[512];
__device__ float g_q[512];
__device__ float g_ctx[128 * 512];
__device__ float g_Gpre[27u * 128u * 2048u];   // 28.3 MB
__device__ float g_H2[27u * 128u * 512u];      // 7.1 MB
__device__ float g_c[2][128 * 512];
__device__ float g_part[8u * 128u * 2048u];    // 8.4 MB

// ---------------- packed fp32x2 helpers ----------------
__device__ __forceinline__ unsigned long long pack2(float x) {
    unsigned long long r;
    asm("mov.b64 %0, {%1, %1};" : "=l"(r) : "f"(x));
    return r;
}
__device__ __forceinline__ void ffma2(unsigned long long& d, unsigned long long a, unsigned long long b) {
    asm("fma.rn.f32x2 %0, %1, %2, %0;" : "+l"(d) : "l"(a), "l"(b));
}
__device__ __forceinline__ float2 unpack2(unsigned long long v) {
    float lo, hi;
    asm("mov.b64 {%0, %1}, %2;" : "=f"(lo), "=f"(hi) : "l"(v));
    return make_float2(lo, hi);
}

// ---------------- fold kernel: matvec out[k] = sum_j vin[j] * W[j,k] ----------
__global__ void mv_kernel(const float* __restrict__ W, int stride,
                          const float* __restrict__ vin_arg, int sin, int sout) {
    const float* vin = (sin == 0) ? vin_arg : (sin == 1 ? g_v0 : g_v1);
    float* vout = (sout == 1) ? g_v0 : (sout == 2 ? g_v1 : g_q);
    int k = blockIdx.x * 32 + threadIdx.x;
    float a0 = 0.f, a1 = 0.f, a2 = 0.f, a3 = 0.f;
    for (int j = 0; j < 512; j += 4) {
        a0 += vin[j + 0] * W[(size_t)(j + 0) * stride + k];
        a1 += vin[j + 1] * W[(size_t)(j + 1) * stride + k];
        a2 += vin[j + 2] * W[(size_t)(j + 2) * stride + k];
        a3 += vin[j + 3] * W[(size_t)(j + 3) * stride + k];
    }
    vout[k] = (a0 + a1) + (a2 + a3);
}

// ---------------- attention: scores = enc . q ; softmax ; ctx ------------------
__global__ void attention_kernel(const float* __restrict__ enc) {
    __shared__ float sq[512];
    __shared__ float sc[80];
    int tid = threadIdx.x;
    int b = blockIdx.x;
    sq[tid] = g_q[tid];
    sq[tid + 256] = g_q[tid + 256];
    __syncthreads();
    int w = tid >> 5, lane = tid & 31;
    for (int s = w; s < 80; s += 8) {
        const float* e = enc + ((size_t)b * 80 + s) * 512;
        float acc = 0.f;
        for (int k = lane; k < 512; k += 32) acc += e[k] * sq[k];
        #pragma unroll
        for (int o = 16; o; o >>= 1) acc += __shfl_xor_sync(0xffffffffu, acc, o);
        if (lane == 0) sc[s] = acc;
    }
    __syncthreads();
    if (tid < 32) {
        float m = -1e30f;
        for (int s = tid; s < 80; s += 32) m = fmaxf(m, sc[s]);
        #pragma unroll
        for (int o = 16; o; o >>= 1) m = fmaxf(m, __shfl_xor_sync(0xffffffffu, m, o));
        float sum = 0.f;
        for (int s = tid; s < 80; s += 32) { float e = expf(sc[s] - m); sc[s] = e; sum += e; }
        #pragma unroll
        for (int o = 16; o; o >>= 1) sum += __shfl_xor_sync(0xffffffffu, sum, o);
        float inv = 1.f / sum;
        for (int s = tid; s < 80; s += 32) sc[s] *= inv;
    }
    __syncthreads();
    for (int k = tid; k < 512; k += 256) {
        float a = 0.f;
        #pragma unroll 8
        for (int s = 0; s < 80; s++) a += sc[s] * enc[((size_t)b * 80 + s) * 512 + k];
        g_ctx[b * 512 + k] = a;
    }
}

// ---------------- shared GEMM core pieces --------------------------------------
// Tile: 128(M) x 128(N) x 16(K), 256 threads, 8x8 per thread via f32x2 (8x4 packs)
__device__ __forceinline__ void tile_fma(const float* As, const float* Bs, int tr, int tc,
                                         unsigned long long acc[8][4]) {
    #pragma unroll
    for (int kk = 0; kk < 16; kk++) {
        float4 a0 = *(const float4*)(As + kk * 128 + tr * 4);
        float4 a1 = *(const float4*)(As + kk * 128 + 64 + tr * 4);
        ulonglong2 b0 = *(const ulonglong2*)(Bs + kk * 128 + tc * 4);
        ulonglong2 b1 = *(const ulonglong2*)(Bs + kk * 128 + 64 + tc * 4);
        unsigned long long pb0 = b0.x, pb1 = b0.y, pb2 = b1.x, pb3 = b1.y;
        float av[8] = {a0.x, a0.y, a0.z, a0.w, a1.x, a1.y, a1.z, a1.w};
        #pragma unroll
        for (int i = 0; i < 8; i++) {
            unsigned long long pa = pack2(av[i]);
            ffma2(acc[i][0], pa, pb0);
            ffma2(acc[i][1], pa, pb1);
            ffma2(acc[i][2], pa, pb2);
            ffma2(acc[i][3], pa, pb3);
        }
    }
}

__device__ __forceinline__ void load_tileB(float* Bs, const float* __restrict__ Wm,
                                           int nbase, int Ntot, int Kstride, int k0,
                                           int lr, int lc) {
    #pragma unroll
    for (int p = 0; p < 2; p++) {
        int n = nbase + lr + p * 64;
        float4 v = make_float4(0.f, 0.f, 0.f, 0.f);
        if (n < Ntot) v = *(const float4*)(Wm + (size_t)n * Kstride + k0 + lc);
        float* d = Bs + lr + p * 64;
        d[(lc + 0) * 128] = v.x;
        d[(lc + 1) * 128] = v.y;
        d[(lc + 2) * 128] = v.z;
        d[(lc + 3) * 128] = v.w;
    }
}

// ---------------- Gpre = [emb(tok), ctx] @ W_ih^T + b_ih + b_hh ----------------
__global__ void __launch_bounds__(256, 2) gpre_gemm(
    const int* __restrict__ targets, const float* __restrict__ emb,
    const float* __restrict__ Wih, const float* __restrict__ bih,
    const float* __restrict__ bhh) {
    __shared__ float As[16 * 128];
    __shared__ float Bs[16 * 128];
    __shared__ int tok[128];
    int t = blockIdx.y;
    int nbase = blockIdx.x * 128;
    int tid = threadIdx.x;
    if (tid < 128) tok[tid] = targets[tid * 28 + t];
    __syncthreads();
    int tr = tid >> 4, tc = tid & 15;
    int lr = tid >> 2, lc = (tid & 3) << 2;
    unsigned long long acc[8][4];
    #pragma unroll
    for (int i = 0; i < 8; i++)
        #pragma unroll
        for (int j = 0; j < 4; j++) acc[i][j] = 0ull;
    for (int k0 = 0; k0 < 1024; k0 += 16) {
        #pragma unroll
        for (int p = 0; p < 2; p++) {
            int r = lr + p * 64;
            const float* ap;
            int c;
            if (k0 < 512) { ap = emb + (size_t)tok[r] * 512; c = k0 + lc; }
            else          { ap = g_ctx + (size_t)r * 512;    c = k0 - 512 + lc; }
            float4 v = *(const float4*)(ap + c);
            float* d = As + r;
            d[(lc + 0) * 128] = v.x; d[(lc + 1) * 128] = v.y;
            d[(lc + 2) * 128] = v.z; d[(lc + 3) * 128] = v.w;
        }
        load_tileB(Bs, Wih, nbase, 2048, 1024, k0, lr, lc);
        __syncthreads();
        tile_fma(As, Bs, tr, tc, acc);
        __syncthreads();
    }
    #pragma unroll
    for (int i = 0; i < 8; i++) {
        int b = (i < 4) ? tr * 4 + i : 64 + tr * 4 + (i - 4);
        float* dst = g_Gpre + ((size_t)t * 128 + b) * 2048;
        #pragma unroll
        for (int j = 0; j < 4; j++) {
            int nc = nbase + ((j >> 1) << 6) + tc * 4 + ((j & 1) << 1);
            float2 v = unpack2(acc[i][j]);
            dst[nc] = v.x + bih[nc] + bhh[nc];
            dst[nc + 1] = v.y + bih[nc + 1] + bhh[nc + 1];
        }
    }
}

// ---------------- per-step h @ W_hh^T (split-K 8, partials, deterministic) -----
__global__ void __launch_bounds__(256, 2) hwhh_gemm(int t, const float* __restrict__ elhs,
                                                    const float* __restrict__ Whh) {
    __shared__ float As[16 * 128];
    __shared__ float Bs[16 * 128];
    int nbase = blockIdx.x * 128;
    int ks = blockIdx.y;
    int tid = threadIdx.x;
    int tr = tid >> 4, tc = tid & 15;
    int lr = tid >> 2, lc = (tid & 3) << 2;
    const float* A = (t == 0) ? elhs : (g_H2 + (size_t)(t - 1) * 128 * 512);
    unsigned long long acc[8][4];
    #pragma unroll
    for (int i = 0; i < 8; i++)
        #pragma unroll
        for (int j = 0; j < 4; j++) acc[i][j] = 0ull;
    int kend = ks * 64 + 64;
    for (int k0 = ks * 64; k0 < kend; k0 += 16) {
        #pragma unroll
        for (int p = 0; p < 2; p++) {
            int r = lr + p * 64;
            float4 v = *(const float4*)(A + (size_t)r * 512 + k0 + lc);
            float* d = As + r;
            d[(lc + 0) * 128] = v.x; d[(lc + 1) * 128] = v.y;
            d[(lc + 2) * 128] = v.z; d[(lc + 3) * 128] = v.w;
        }
        load_tileB(Bs, Whh, nbase, 2048, 512, k0, lr, lc);
        __syncthreads();
        tile_fma(As, Bs, tr, tc, acc);
        __syncthreads();
    }
    #pragma unroll
    for (int i = 0; i < 8; i++) {
        int b = (i < 4) ? tr * 4 + i : 64 + tr * 4 + (i - 4);
        float* dst = g_part + ((size_t)ks * 128 + b) * 2048;
        #pragma unroll
        for (int j = 0; j < 4; j++) {
            int nc = nbase + ((j >> 1) << 6) + tc * 4 + ((j & 1) << 1);
            float2 v = unpack2(acc[i][j]);
            dst[nc] = v.x;
            dst[nc + 1] = v.y;
        }
    }
}

// ---------------- reduce partials + LSTM pointwise -----------------------------
__global__ void lstm_point(int t) {
    int idx = blockIdx.x * 256 + threadIdx.x;  // 0..65535
    int b = idx >> 9, j = idx & 511;
    const float* gp = g_Gpre + ((size_t)t * 128 + b) * 2048;
    float gi = gp[j], gf = gp[j + 512], gg = gp[j + 1024], go = gp[j + 1536];
    #pragma unroll
    for (int ks = 0; ks < 8; ks++) {
        const float* pp = g_part + ((size_t)ks * 128 + b) * 2048;
        gi += pp[j]; gf += pp[j + 512]; gg += pp[j + 1024]; go += pp[j + 1536];
    }
    float cprev = (t == 0) ? 0.f : g_c[(t - 1) & 1][b * 512 + j];
    float si = 1.f / (1.f + expf(-gi));
    float sf = 1.f / (1.f + expf(-gf));
    float so = 1.f / (1.f + expf(-go));
    float c2 = sf * cprev + si * tanhf(gg);
    float h2 = so * tanhf(c2);
    g_c[t & 1][b * 512 + j] = c2;
    g_H2[(size_t)t * 128 * 512 + b * 512 + j] = h2;
}

// ---------------- logits = H2 @ W_out^T + b_out --------------------------------
__global__ void __launch_bounds__(256, 2) logits_gemm(const float* __restrict__ Wout,
                                                      const float* __restrict__ bout,
                                                      float* __restrict__ out) {
    __shared__ float As[16 * 128];
    __shared__ float Bs[16 * 128];
    int t = blockIdx.y;
    int nbase = blockIdx.x * 128;
    int tid = threadIdx.x;
    int tr = tid >> 4, tc = tid & 15;
    int lr = tid >> 2, lc = (tid & 3) << 2;
    const float* A = g_H2 + (size_t)t * 128 * 512;
    unsigned long long acc[8][4];
    #pragma unroll
    for (int i = 0; i < 8; i++)
        #pragma unroll
        for (int j = 0; j < 4; j++) acc[i][j] = 0ull;
    for (int k0 = 0; k0 < 512; k0 += 16) {
        #pragma unroll
        for (int p = 0; p < 2; p++) {
            int r = lr + p * 64;
            float4 v = *(const float4*)(A + (size_t)r * 512 + k0 + lc);
            float* d = As + r;
            d[(lc + 0) * 128] = v.x; d[(lc + 1) * 128] = v.y;
            d[(lc + 2) * 128] = v.z; d[(lc + 3) * 128] = v.w;
        }
        load_tileB(Bs, Wout, nbase, Vv, 512, k0, lr, lc);
        __syncthreads();
        tile_fma(As, Bs, tr, tc, acc);
        __syncthreads();
    }
    #pragma unroll
    for (int i = 0; i < 8; i++) {
        int b = (i < 4) ? tr * 4 + i : 64 + tr * 4 + (i - 4);
        size_t row = (size_t)(b * 27 + t) * Vv;
        #pragma unroll
        for (int j = 0; j < 4; j++) {
            int nc = nbase + ((j >> 1) << 6) + tc * 4 + ((j & 1) << 1);
            if (nc < Vv) {  // Vv even, nc even -> pair fully valid
                float2 v = unpack2(acc[i][j]);
                out[row + nc] = v.x + bout[nc];
                out[row + nc + 1] = v.y + bout[nc + 1];
            }
        }
    }
}

// ---------------- argmax (first-max tie-break, matches jnp.argmax) -------------
__global__ void argmax_kernel(const float* __restrict__ logits, float* __restrict__ preds) {
    __shared__ float sv[256];
    __shared__ int si[256];
    int r = blockIdx.x;
    const float* row = logits + (size_t)r * Vv;
    int tid = threadIdx.x;
    float best = -3.4e38f;
    int bi = 0x7fffffff;
    for (int n = tid; n < Vv; n += 256) {
        float v = row[n];
        if (v > best) { best = v; bi = n; }
    }
    sv[tid] = best; si[tid] = bi;
    __syncthreads();
    for (int o = 128; o; o >>= 1) {
        if (tid < o) {
            float v2 = sv[tid + o]; int i2 = si[tid + o];
            if (v2 > sv[tid] || (v2 == sv[tid] && i2 < si[tid])) { sv[tid] = v2; si[tid] = i2; }
        }
        __syncthreads();
    }
    if (tid == 0) preds[r] = (float)si[0];
}

// -------------------------------------------------------------------------------
extern "C" void kernel_launch(void* const* d_in, const int* in_sizes, int n_in,
                              void* d_out, int out_size) {
    const float* elhs    = (const float*)d_in[0];   // (1,128,512)
    const float* enc     = (const float*)d_in[1];   // (128,80,512)
    const int*   targets = (const int*)d_in[2];     // (128,28)
    const float* emb     = (const float*)d_in[3];   // (30000,512)
    const float* W1      = (const float*)d_in[4];   // (512,1024)
    const float* W2      = (const float*)d_in[6];   // (512,512)
    const float* W3      = (const float*)d_in[8];
    const float* W4      = (const float*)d_in[10];
    const float* w_att   = (const float*)d_in[12];  // (1,512)
    const float* W_ih    = (const float*)d_in[13];  // (2048,1024)
    const float* W_hh    = (const float*)d_in[14];  // (2048,512)
    const float* b_ih    = (const float*)d_in[15];
    const float* b_hh    = (const float*)d_in[16];
    const float* W_out   = (const float*)d_in[17];  // (30000,512)
    const float* b_out   = (const float*)d_in[18];
    float* out = (float*)d_out;

    // fold attention MLP into one vector q (b1..b4 drop out via softmax shift-invariance)
    mv_kernel<<<16, 32>>>(W4, 512, w_att, 0, 1);   // v0 = W4^T w
    mv_kernel<<<16, 32>>>(W3, 512, nullptr, 1, 2); // v1 = W3^T v0
    mv_kernel<<<16, 32>>>(W2, 512, nullptr, 2, 1); // v0 = W2^T v1
    mv_kernel<<<16, 32>>>(W1, 1024, nullptr, 1, 3);// q  = W1[:, :512]^T v0

    attention_kernel<<<128, 256>>>(enc);           // ctx per batch (time-invariant)

    gpre_gemm<<<dim3(16, 27), 256>>>(targets, emb, W_ih, b_ih, b_hh);

    for (int t = 0; t < 27; t++) {
        hwhh_gemm<<<dim3(16, 8), 256>>>(t, elhs, W_hh);
        lstm_point<<<256, 256>>>(t);
    }

    logits_gemm<<<dim3(235, 27), 256>>>(W_out, b_out, out);

    long long main_sz = (long long)3456 * Vv;
    if ((long long)out_size > main_sz)
        argmax_kernel<<<3456, 256>>>(out, out + main_sz);
}

// round 2
// speedup vs baseline: 1.0404x; 1.0404x over previous
#include <cuda_runtime.h>
#include <math.h>

// ----------------------------------------------------------------------------
// DecoderLSTMWithAttention — R2:
//   - attention folded (time-invariant softmax), projections hoisted (as R1)
//   - persistent single-kernel LSTM chain (software grid barrier)
//   - double-buffered, single-sync-per-Ktile FFMA2 GEMMs (logits, gpre)
//   - K-parallel matvec fold, float4 argmax
// ----------------------------------------------------------------------------

#define Bb 128
#define Hh 512
#define Ss 80
#define Tt 27
#define Vv 30000
#define NBLK_CHAIN 128

// scratch (device globals: no allocations allowed)
__device__ float g_v0[512];
__device__ float g_v1[512];
__device__ float g_q[512];
__device__ float g_ctx[128 * 512];
__device__ float g_Gpre[27u * 128u * 2048u];   // 28.3 MB
__device__ float g_H2[27u * 128u * 512u];      // 7.1 MB
__device__ float g_c[2][128 * 512];
__device__ float g_part[8u * 128u * 2048u];    // 8.4 MB
__device__ unsigned g_bar_cnt;
__device__ unsigned g_bar_gen;

// ---------------- packed fp32x2 helpers ----------------
__device__ __forceinline__ unsigned long long pack2(float x) {
    unsigned long long r;
    asm("mov.b64 %0, {%1, %1};" : "=l"(r) : "f"(x));
    return r;
}
__device__ __forceinline__ void ffma2(unsigned long long& d, unsigned long long a, unsigned long long b) {
    asm("fma.rn.f32x2 %0, %1, %2, %0;" : "+l"(d) : "l"(a), "l"(b));
}
__device__ __forceinline__ float2 unpack2(unsigned long long v) {
    float lo, hi;
    asm("mov.b64 {%0, %1}, %2;" : "=f"(lo), "=f"(hi) : "l"(v));
    return make_float2(lo, hi);
}

// ---------------- barrier init ----------------
__global__ void bar_init_kernel() { g_bar_cnt = 0; g_bar_gen = 0; }

// software grid barrier (all NBLK_CHAIN blocks resident; grid < #SMs)
__device__ __forceinline__ void gsync(unsigned target) {
    __syncthreads();
    if (threadIdx.x == 0) {
        __threadfence();
        unsigned prev = atomicAdd(&g_bar_cnt, 1u);
        if (prev == NBLK_CHAIN - 1) {
            g_bar_cnt = 0;
            __threadfence();
            *(volatile unsigned*)&g_bar_gen = target;
        } else {
            volatile unsigned* vg = (volatile unsigned*)&g_bar_gen;
            while (*vg < target) { __nanosleep(32); }
        }
        __threadfence();
    }
    __syncthreads();
}

// ---------------- fold matvec: out[k] = sum_j vin[j] * W[j,k] ------------------
// grid 8 x 256: block computes 64 outputs, 4 j-stripes of 128 each
__global__ void mv_kernel(const float* __restrict__ W, int stride,
                          const float* __restrict__ vin_arg, int sin, int sout) {
    __shared__ float red[4][64];
    const float* vin = (sin == 0) ? vin_arg : (sin == 1 ? g_v0 : g_v1);
    float* vout = (sout == 1) ? g_v0 : (sout == 2 ? g_v1 : g_q);
    int klocal = threadIdx.x & 63;
    int s = threadIdx.x >> 6;
    int k = blockIdx.x * 64 + klocal;
    float a0 = 0.f, a1 = 0.f, a2 = 0.f, a3 = 0.f;
    int j0 = s * 128;
    #pragma unroll 8
    for (int j = 0; j < 128; j += 4) {
        a0 += vin[j0 + j + 0] * W[(size_t)(j0 + j + 0) * stride + k];
        a1 += vin[j0 + j + 1] * W[(size_t)(j0 + j + 1) * stride + k];
        a2 += vin[j0 + j + 2] * W[(size_t)(j0 + j + 2) * stride + k];
        a3 += vin[j0 + j + 3] * W[(size_t)(j0 + j + 3) * stride + k];
    }
    red[s][klocal] = (a0 + a1) + (a2 + a3);
    __syncthreads();
    if (threadIdx.x < 64)
        vout[blockIdx.x * 64 + threadIdx.x] =
            (red[0][threadIdx.x] + red[1][threadIdx.x]) +
            (red[2][threadIdx.x] + red[3][threadIdx.x]);
}

// ---------------- attention: scores = enc . q ; softmax ; ctx ------------------
__global__ void attention_kernel(const float* __restrict__ enc) {
    __shared__ float sq[512];
    __shared__ float sc[80];
    int tid = threadIdx.x;
    int b = blockIdx.x;
    sq[tid] = g_q[tid];
    sq[tid + 256] = g_q[tid + 256];
    __syncthreads();
    int w = tid >> 5, lane = tid & 31;
    for (int s = w; s < 80; s += 8) {
        const float* e = enc + ((size_t)b * 80 + s) * 512;
        float acc = 0.f;
        for (int k = lane; k < 512; k += 32) acc += e[k] * sq[k];
        #pragma unroll
        for (int o = 16; o; o >>= 1) acc += __shfl_xor_sync(0xffffffffu, acc, o);
        if (lane == 0) sc[s] = acc;
    }
    __syncthreads();
    if (tid < 32) {
        float m = -1e30f;
        for (int s = tid; s < 80; s += 32) m = fmaxf(m, sc[s]);
        #pragma unroll
        for (int o = 16; o; o >>= 1) m = fmaxf(m, __shfl_xor_sync(0xffffffffu, m, o));
        float sum = 0.f;
        for (int s = tid; s < 80; s += 32) { float e = expf(sc[s] - m); sc[s] = e; sum += e; }
        #pragma unroll
        for (int o = 16; o; o >>= 1) sum += __shfl_xor_sync(0xffffffffu, sum, o);
        float inv = 1.f / sum;
        for (int s = tid; s < 80; s += 32) sc[s] *= inv;
    }
    __syncthreads();
    for (int k = tid; k < 512; k += 256) {
        float a = 0.f;
        #pragma unroll 8
        for (int s = 0; s < 80; s++) a += sc[s] * enc[((size_t)b * 80 + s) * 512 + k];
        g_ctx[b * 512 + k] = a;
    }
}

// ---------------- GEMM micro-kernel: 128x128x16 tile, 8x8/thread via f32x2 -----
__device__ __forceinline__ void tile_fma(const float* As, const float* Bs, int tr, int tc,
                                         unsigned long long acc[8][4]) {
    #pragma unroll
    for (int kk = 0; kk < 16; kk++) {
        float4 a0 = *(const float4*)(As + kk * 128 + tr * 4);
        float4 a1 = *(const float4*)(As + kk * 128 + 64 + tr * 4);
        ulonglong2 b0 = *(const ulonglong2*)(Bs + kk * 128 + tc * 4);
        ulonglong2 b1 = *(const ulonglong2*)(Bs + kk * 128 + 64 + tc * 4);
        unsigned long long pb0 = b0.x, pb1 = b0.y, pb2 = b1.x, pb3 = b1.y;
        float av[8] = {a0.x, a0.y, a0.z, a0.w, a1.x, a1.y, a1.z, a1.w};
        #pragma unroll
        for (int i = 0; i < 8; i++) {
            unsigned long long pa = pack2(av[i]);
            ffma2(acc[i][0], pa, pb0);
            ffma2(acc[i][1], pa, pb1);
            ffma2(acc[i][2], pa, pb2);
            ffma2(acc[i][3], pa, pb3);
        }
    }
}

// transpose-store a float4 (4 consecutive k) for row r into [k][row128] tile
__device__ __forceinline__ void stT(float* S, int r, int lc, float4 v) {
    float* d = S + r;
    d[(lc + 0) * 128] = v.x;
    d[(lc + 1) * 128] = v.y;
    d[(lc + 2) * 128] = v.z;
    d[(lc + 3) * 128] = v.w;
}

// ---------------- Gpre = [emb(tok), ctx] @ W_ih^T + b_ih + b_hh ----------------
__global__ void __launch_bounds__(256, 2) gpre_gemm(
    const int* __restrict__ targets, const float* __restrict__ emb,
    const float* __restrict__ Wih, const float* __restrict__ bih,
    const float* __restrict__ bhh) {
    __shared__ float As[2][16 * 128];
    __shared__ float Bs[2][16 * 128];
    __shared__ int tok[128];
    int t = blockIdx.y;
    int nbase = blockIdx.x * 128;
    int tid = threadIdx.x;
    if (tid < 128) tok[tid] = targets[tid * 28 + t];
    __syncthreads();
    int tr = tid >> 4, tc = tid & 15;
    int lr = tid >> 2, lc = (tid & 3) << 2;
    unsigned long long acc[8][4];
    #pragma unroll
    for (int i = 0; i < 8; i++)
        #pragma unroll
        for (int j = 0; j < 4; j++) acc[i][j] = 0ull;

    float4 ra0, ra1, rb0, rb1;
    // prologue loads (k0 = 0 < 512 -> emb side)
    ra0 = *(const float4*)(emb + (size_t)tok[lr] * 512 + lc);
    ra1 = *(const float4*)(emb + (size_t)tok[lr + 64] * 512 + lc);
    rb0 = *(const float4*)(Wih + (size_t)(nbase + lr) * 1024 + lc);
    rb1 = *(const float4*)(Wih + (size_t)(nbase + lr + 64) * 1024 + lc);
    stT(As[0], lr, lc, ra0); stT(As[0], lr + 64, lc, ra1);
    stT(Bs[0], lr, lc, rb0); stT(Bs[0], lr + 64, lc, rb1);
    __syncthreads();

    int cur = 0;
    for (int kt = 0; kt < 64; kt++) {
        if (kt < 63) {
            int k0 = (kt + 1) * 16;
            if (k0 < 512) {
                ra0 = *(const float4*)(emb + (size_t)tok[lr] * 512 + k0 + lc);
                ra1 = *(const float4*)(emb + (size_t)tok[lr + 64] * 512 + k0 + lc);
            } else {
                ra0 = *(const float4*)(g_ctx + (size_t)lr * 512 + (k0 - 512) + lc);
                ra1 = *(const float4*)(g_ctx + (size_t)(lr + 64) * 512 + (k0 - 512) + lc);
            }
            rb0 = *(const float4*)(Wih + (size_t)(nbase + lr) * 1024 + k0 + lc);
            rb1 = *(const float4*)(Wih + (size_t)(nbase + lr + 64) * 1024 + k0 + lc);
        }
        tile_fma(As[cur], Bs[cur], tr, tc, acc);
        if (kt < 63) {
            stT(As[cur ^ 1], lr, lc, ra0); stT(As[cur ^ 1], lr + 64, lc, ra1);
            stT(Bs[cur ^ 1], lr, lc, rb0); stT(Bs[cur ^ 1], lr + 64, lc, rb1);
        }
        __syncthreads();
        cur ^= 1;
    }
    #pragma unroll
    for (int i = 0; i < 8; i++) {
        int b = (i < 4) ? tr * 4 + i : 64 + tr * 4 + (i - 4);
        float* dst = g_Gpre + ((size_t)t * 128 + b) * 2048;
        #pragma unroll
        for (int j = 0; j < 4; j++) {
            int nc = nbase + ((j >> 1) << 6) + tc * 4 + ((j & 1) << 1);
            float2 v = unpack2(acc[i][j]);
            dst[nc] = v.x + bih[nc] + bhh[nc];
            dst[nc + 1] = v.y + bih[nc + 1] + bhh[nc + 1];
        }
    }
}

// ---------------- persistent LSTM chain: 27 x (h@W_hh^T splitK + pointwise) ----
__global__ void __launch_bounds__(256, 1) lstm_chain(const float* __restrict__ elhs,
                                                     const float* __restrict__ Whh) {
    __shared__ float As[2][16 * 128];
    __shared__ float Bs[2][16 * 128];
    int tid = threadIdx.x;
    int nbase = (blockIdx.x & 15) * 128;
    int ks = blockIdx.x >> 4;           // 0..7, K range [ks*64, ks*64+64)
    int tr = tid >> 4, tc = tid & 15;
    int lr = tid >> 2, lc = (tid & 3) << 2;
    unsigned epoch = 0;

    for (int t = 0; t < 27; t++) {
        const float* A = (t == 0) ? elhs : (g_H2 + (size_t)(t - 1) * 128 * 512);
        unsigned long long acc[8][4];
        #pragma unroll
        for (int i = 0; i < 8; i++)
            #pragma unroll
            for (int j = 0; j < 4; j++) acc[i][j] = 0ull;

        int kbeg = ks * 64;
        float4 ra0, ra1, rb0, rb1;
        ra0 = *(const float4*)(A + (size_t)lr * 512 + kbeg + lc);
        ra1 = *(const float4*)(A + (size_t)(lr + 64) * 512 + kbeg + lc);
        rb0 = *(const float4*)(Whh + (size_t)(nbase + lr) * 512 + kbeg + lc);
        rb1 = *(const float4*)(Whh + (size_t)(nbase + lr + 64) * 512 + kbeg + lc);
        stT(As[0], lr, lc, ra0); stT(As[0], lr + 64, lc, ra1);
        stT(Bs[0], lr, lc, rb0); stT(Bs[0], lr + 64, lc, rb1);
        __syncthreads();
        int cur = 0;
        #pragma unroll
        for (int kt = 0; kt < 4; kt++) {
            if (kt < 3) {
                int k0 = kbeg + (kt + 1) * 16;
                ra0 = *(const float4*)(A + (size_t)lr * 512 + k0 + lc);
                ra1 = *(const float4*)(A + (size_t)(lr + 64) * 512 + k0 + lc);
                rb0 = *(const float4*)(Whh + (size_t)(nbase + lr) * 512 + k0 + lc);
                rb1 = *(const float4*)(Whh + (size_t)(nbase + lr + 64) * 512 + k0 + lc);
            }
            tile_fma(As[cur], Bs[cur], tr, tc, acc);
            if (kt < 3) {
                stT(As[cur ^ 1], lr, lc, ra0); stT(As[cur ^ 1], lr + 64, lc, ra1);
                stT(Bs[cur ^ 1], lr, lc, rb0); stT(Bs[cur ^ 1], lr + 64, lc, rb1);
            }
            __syncthreads();
            cur ^= 1;
        }
        // write partials
        #pragma unroll
        for (int i = 0; i < 8; i++) {
            int b = (i < 4) ? tr * 4 + i : 64 + tr * 4 + (i - 4);
            float* dst = g_part + ((size_t)ks * 128 + b) * 2048;
            #pragma unroll
            for (int j = 0; j < 4; j++) {
                int nc = nbase + ((j >> 1) << 6) + tc * 4 + ((j & 1) << 1);
                float2 v = unpack2(acc[i][j]);
                dst[nc] = v.x;
                dst[nc + 1] = v.y;
            }
        }
        gsync(++epoch);

        // pointwise LSTM (2 elems/thread); cross-SM data -> __ldcg (bypass L1)
        #pragma unroll
        for (int e = 0; e < 2; e++) {
            int idx = e * 32768 + blockIdx.x * 256 + tid;
            int b = idx >> 9, j = idx & 511;
            const float* gp = g_Gpre + ((size_t)t * 128 + b) * 2048;
            float gi = gp[j], gf = gp[j + 512], gg = gp[j + 1024], go = gp[j + 1536];
            #pragma unroll
            for (int kk = 0; kk < 8; kk++) {
                const float* pp = g_part + ((size_t)kk * 128 + b) * 2048;
                gi += __ldcg(pp + j);
                gf += __ldcg(pp + j + 512);
                gg += __ldcg(pp + j + 1024);
                go += __ldcg(pp + j + 1536);
            }
            float cprev = (t == 0) ? 0.f : __ldcg(&g_c[(t - 1) & 1][b * 512 + j]);
            float si = 1.f / (1.f + expf(-gi));
            float sf = 1.f / (1.f + expf(-gf));
            float so = 1.f / (1.f + expf(-go));
            float c2 = sf * cprev + si * tanhf(gg);
            float h2 = so * tanhf(c2);
            g_c[t & 1][b * 512 + j] = c2;
            g_H2[(size_t)t * 128 * 512 + b * 512 + j] = h2;
        }
        gsync(++epoch);
    }
}

// ---------------- logits = H2 @ W_out^T + b_out --------------------------------
__global__ void __launch_bounds__(256, 2) logits_gemm(const float* __restrict__ Wout,
                                                      const float* __restrict__ bout,
                                                      float* __restrict__ out) {
    __shared__ float As[2][16 * 128];
    __shared__ float Bs[2][16 * 128];
    int t = blockIdx.y;
    int nbase = blockIdx.x * 128;
    int tid = threadIdx.x;
    int tr = tid >> 4, tc = tid & 15;
    int lr = tid >> 2, lc = (tid & 3) << 2;
    const float* A = g_H2 + (size_t)t * 128 * 512;
    int n0 = nbase + lr, n1 = nbase + lr + 64;
    bool v0 = n0 < Vv, v1 = n1 < Vv;
    unsigned long long acc[8][4];
    #pragma unroll
    for (int i = 0; i < 8; i++)
        #pragma unroll
        for (int j = 0; j < 4; j++) acc[i][j] = 0ull;

    float4 ra0, ra1, rb0, rb1;
    const float4 f4z = make_float4(0.f, 0.f, 0.f, 0.f);
    ra0 = *(const float4*)(A + (size_t)lr * 512 + lc);
    ra1 = *(const float4*)(A + (size_t)(lr + 64) * 512 + lc);
    rb0 = v0 ? *(const float4*)(Wout + (size_t)n0 * 512 + lc) : f4z;
    rb1 = v1 ? *(const float4*)(Wout + (size_t)n1 * 512 + lc) : f4z;
    stT(As[0], lr, lc, ra0); stT(As[0], lr + 64, lc, ra1);
    stT(Bs[0], lr, lc, rb0); stT(Bs[0], lr + 64, lc, rb1);
    __syncthreads();

    int cur = 0;
    for (int kt = 0; kt < 32; kt++) {
        if (kt < 31) {
            int k0 = (kt + 1) * 16;
            ra0 = *(const float4*)(A + (size_t)lr * 512 + k0 + lc);
            ra1 = *(const float4*)(A + (size_t)(lr + 64) * 512 + k0 + lc);
            rb0 = v0 ? *(const float4*)(Wout + (size_t)n0 * 512 + k0 + lc) : f4z;
            rb1 = v1 ? *(const float4*)(Wout + (size_t)n1 * 512 + k0 + lc) : f4z;
        }
        tile_fma(As[cur], Bs[cur], tr, tc, acc);
        if (kt < 31) {
            stT(As[cur ^ 1], lr, lc, ra0); stT(As[cur ^ 1], lr + 64, lc, ra1);
            stT(Bs[cur ^ 1], lr, lc, rb0); stT(Bs[cur ^ 1], lr + 64, lc, rb1);
        }
        __syncthreads();
        cur ^= 1;
    }
    #pragma unroll
    for (int i = 0; i < 8; i++) {
        int b = (i < 4) ? tr * 4 + i : 64 + tr * 4 + (i - 4);
        size_t row = (size_t)(b * 27 + t) * Vv;
        #pragma unroll
        for (int j = 0; j < 4; j++) {
            int nc = nbase + ((j >> 1) << 6) + tc * 4 + ((j & 1) << 1);
            if (nc < Vv) {  // Vv even, nc even -> pair fully valid
                float2 v = unpack2(acc[i][j]);
                out[row + nc] = v.x + bout[nc];
                out[row + nc + 1] = v.y + bout[nc + 1];
            }
        }
    }
}

// ---------------- argmax (first-max tie-break, float4 reads) -------------------
__global__ void argmax_kernel(const float* __restrict__ logits, float* __restrict__ preds) {
    __shared__ float sv[256];
    __shared__ int si[256];
    int r = blockIdx.x;
    const float4* row = (const float4*)(logits + (size_t)r * Vv);  // 30000 % 4 == 0
    int tid = threadIdx.x;
    float best = -3.4e38f;
    int bi = 0x7fffffff;
    for (int q = tid; q < Vv / 4; q += 256) {
        float4 v = row[q];
        int n = q * 4;
        if (v.x > best) { best = v.x; bi = n; }
        if (v.y > best) { best = v.y; bi = n + 1; }
        if (v.z > best) { best = v.z; bi = n + 2; }
        if (v.w > best) { best = v.w; bi = n + 3; }
    }
    sv[tid] = best; si[tid] = bi;
    __syncthreads();
    for (int o = 128; o; o >>= 1) {
        if (tid < o) {
            float v2 = sv[tid + o]; int i2 = si[tid + o];
            if (v2 > sv[tid] || (v2 == sv[tid] && i2 < si[tid])) { sv[tid] = v2; si[tid] = i2; }
        }
        __syncthreads();
    }
    if (tid == 0) preds[r] = (float)si[0];
}

// -------------------------------------------------------------------------------
extern "C" void kernel_launch(void* const* d_in, const int* in_sizes, int n_in,
                              void* d_out, int out_size) {
    const float* elhs    = (const float*)d_in[0];   // (1,128,512)
    const float* enc     = (const float*)d_in[1];   // (128,80,512)
    const int*   targets = (const int*)d_in[2];     // (128,28)
    const float* emb     = (const float*)d_in[3];   // (30000,512)
    const float* W1      = (const float*)d_in[4];   // (512,1024)
    const float* W2      = (const float*)d_in[6];   // (512,512)
    const float* W3      = (const float*)d_in[8];
    const float* W4      = (const float*)d_in[10];
    const float* w_att   = (const float*)d_in[12];  // (1,512)
    const float* W_ih    = (const float*)d_in[13];  // (2048,1024)
    const float* W_hh    = (const float*)d_in[14];  // (2048,512)
    const float* b_ih    = (const float*)d_in[15];
    const float* b_hh    = (const float*)d_in[16];
    const float* W_out   = (const float*)d_in[17];  // (30000,512)
    const float* b_out   = (const float*)d_in[18];
    float* out = (float*)d_out;

    // fold attention MLP into one vector q (biases drop via softmax shift-invariance)
    mv_kernel<<<8, 256>>>(W4, 512, w_att, 0, 1);   // v0 = W4^T w
    mv_kernel<<<8, 256>>>(W3, 512, nullptr, 1, 2); // v1 = W3^T v0
    mv_kernel<<<8, 256>>>(W2, 512, nullptr, 2, 1); // v0 = W2^T v1
    mv_kernel<<<8, 256>>>(W1, 1024, nullptr, 1, 3);// q  = W1[:, :512]^T v0

    attention_kernel<<<128, 256>>>(enc);           // ctx per batch (time-invariant)

    gpre_gemm<<<dim3(16, 27), 256>>>(targets, emb, W_ih, b_ih, b_hh);

    bar_init_kernel<<<1, 1>>>();
    lstm_chain<<<NBLK_CHAIN, 256>>>(elhs, W_hh);

    logits_gemm<<<dim3(235, 27), 256>>>(W_out, b_out, out);

    long long main_sz = (long long)3456 * Vv;
    if ((long long)out_size > main_sz)
        argmax_kernel<<<3456, 256>>>(out, out + main_sz);
}

// round 4
// speedup vs baseline: 1.2451x; 1.1967x over previous
#include <cuda_runtime.h>
#include <cuda_bf16.h>
#include <math.h>
#include <stdint.h>

// ----------------------------------------------------------------------------
// DecoderLSTMWithAttention — R4:
//   - attention folded + hoisted projections (R1), persistent LSTM chain (R2)
//   - logits GEMM on legacy tensor cores (mma.sync bf16, sm_103-safe — tcgen05
//     is rejected by this harness's compute_103 PTX target):
//     3xBF16-split (Ahi*Bhi + Ahi*Blo + Alo*Bhi), fp32 accum,
//     128x128 CTA tile, ldmatrix-native smem layout, 2-stage cp.async pipeline
//   - argmax with deterministic exact-fp32 recheck of near-max candidates
// ----------------------------------------------------------------------------

#define Bb 128
#define Hh 512
#define Tt 27
#define Vv 30000
#define NBLK_CHAIN 128
#define VPAD 30208            // 236*128 > 235*128, pad for guard-free B loads

// scratch (device globals: no allocations allowed)
__device__ float g_v0[512];
__device__ float g_v1[512];
__device__ float g_q[512];
__device__ float g_ctx[128 * 512];
__device__ float g_Gpre[27u * 128u * 2048u];
__device__ float g_H2[27u * 128u * 512u];
__device__ float g_c[2][128 * 512];
__device__ float g_part[8u * 128u * 2048u];
__device__ unsigned g_bar_cnt;
__device__ unsigned g_bar_gen;
// bf16 splits
__device__ __nv_bfloat16 g_Ahi[3456u * 512u];
__device__ __nv_bfloat16 g_Alo[3456u * 512u];
__device__ __nv_bfloat16 g_Whi[(unsigned)VPAD * 512u];
__device__ __nv_bfloat16 g_Wlo[(unsigned)VPAD * 512u];

// ---------------- packed fp32x2 helpers (for gpre/chain FFMA2 GEMMs) ----------
__device__ __forceinline__ unsigned long long pack2(float x) {
    unsigned long long r;
    asm("mov.b64 %0, {%1, %1};" : "=l"(r) : "f"(x));
    return r;
}
__device__ __forceinline__ void ffma2(unsigned long long& d, unsigned long long a, unsigned long long b) {
    asm("fma.rn.f32x2 %0, %1, %2, %0;" : "+l"(d) : "l"(a), "l"(b));
}
__device__ __forceinline__ float2 unpack2(unsigned long long v) {
    float lo, hi;
    asm("mov.b64 {%0, %1}, %2;" : "=f"(lo), "=f"(hi) : "l"(v));
    return make_float2(lo, hi);
}

// ---------------- ptx helpers (all sm_103-base-safe) ----------------------------
__device__ __forceinline__ uint32_t smem_u32(const void* p) {
    uint32_t a;
    asm("{ .reg .u64 t; cvta.to.shared.u64 t, %1; cvt.u32.u64 %0, t; }" : "=r"(a) : "l"(p));
    return a;
}
__device__ __forceinline__ void cp16(uint32_t dst, const void* src) {
    asm volatile("cp.async.cg.shared.global [%0], [%1], 16;" :: "r"(dst), "l"(src));
}
#define CP_COMMIT() asm volatile("cp.async.commit_group;" ::: "memory")
#define CP_WAIT0()  asm volatile("cp.async.wait_group 0;" ::: "memory")
__device__ __forceinline__ void ldm_x4(uint32_t* r, uint32_t addr) {
    asm volatile("ldmatrix.sync.aligned.m8n8.x4.shared.b16 {%0,%1,%2,%3}, [%4];"
        : "=r"(r[0]), "=r"(r[1]), "=r"(r[2]), "=r"(r[3]) : "r"(addr));
}
__device__ __forceinline__ void mma_bf16(float* d, const uint32_t* a, const uint32_t* b) {
    asm volatile("mma.sync.aligned.m16n8k16.row.col.f32.bf16.bf16.f32 "
        "{%0,%1,%2,%3}, {%4,%5,%6,%7}, {%8,%9}, {%0,%1,%2,%3};"
        : "+f"(d[0]), "+f"(d[1]), "+f"(d[2]), "+f"(d[3])
        : "r"(a[0]), "r"(a[1]), "r"(a[2]), "r"(a[3]), "r"(b[0]), "r"(b[1]));
}

// ---------------- barrier init ----------------
__global__ void bar_init_kernel() { g_bar_cnt = 0; g_bar_gen = 0; }

__device__ __forceinline__ void gsync(unsigned target) {
    __syncthreads();
    if (threadIdx.x == 0) {
        __threadfence();
        unsigned prev = atomicAdd(&g_bar_cnt, 1u);
        if (prev == NBLK_CHAIN - 1) {
            g_bar_cnt = 0;
            __threadfence();
            *(volatile unsigned*)&g_bar_gen = target;
        } else {
            volatile unsigned* vg = (volatile unsigned*)&g_bar_gen;
            while (*vg < target) { __nanosleep(32); }
        }
        __threadfence();
    }
    __syncthreads();
}

// ---------------- fold matvec ---------------------------------------------------
__global__ void mv_kernel(const float* __restrict__ W, int stride,
                          const float* __restrict__ vin_arg, int sin, int sout) {
    __shared__ float red[4][64];
    const float* vin = (sin == 0) ? vin_arg : (sin == 1 ? g_v0 : g_v1);
    float* vout = (sout == 1) ? g_v0 : (sout == 2 ? g_v1 : g_q);
    int klocal = threadIdx.x & 63;
    int s = threadIdx.x >> 6;
    int k = blockIdx.x * 64 + klocal;
    float a0 = 0.f, a1 = 0.f, a2 = 0.f, a3 = 0.f;
    int j0 = s * 128;
    #pragma unroll 8
    for (int j = 0; j < 128; j += 4) {
        a0 += vin[j0 + j + 0] * W[(size_t)(j0 + j + 0) * stride + k];
        a1 += vin[j0 + j + 1] * W[(size_t)(j0 + j + 1) * stride + k];
        a2 += vin[j0 + j + 2] * W[(size_t)(j0 + j + 2) * stride + k];
        a3 += vin[j0 + j + 3] * W[(size_t)(j0 + j + 3) * stride + k];
    }
    red[s][klocal] = (a0 + a1) + (a2 + a3);
    __syncthreads();
    if (threadIdx.x < 64)
        vout[blockIdx.x * 64 + threadIdx.x] =
            (red[0][threadIdx.x] + red[1][threadIdx.x]) +
            (red[2][threadIdx.x] + red[3][threadIdx.x]);
}

// ---------------- attention ------------------------------------------------------
__global__ void attention_kernel(const float* __restrict__ enc) {
    __shared__ float sq[512];
    __shared__ float sc[80];
    int tid = threadIdx.x;
    int b = blockIdx.x;
    sq[tid] = g_q[tid];
    sq[tid + 256] = g_q[tid + 256];
    __syncthreads();
    int w = tid >> 5, lane = tid & 31;
    for (int s = w; s < 80; s += 8) {
        const float* e = enc + ((size_t)b * 80 + s) * 512;
        float acc = 0.f;
        for (int k = lane; k < 512; k += 32) acc += e[k] * sq[k];
        #pragma unroll
        for (int o = 16; o; o >>= 1) acc += __shfl_xor_sync(0xffffffffu, acc, o);
        if (lane == 0) sc[s] = acc;
    }
    __syncthreads();
    if (tid < 32) {
        float m = -1e30f;
        for (int s = tid; s < 80; s += 32) m = fmaxf(m, sc[s]);
        #pragma unroll
        for (int o = 16; o; o >>= 1) m = fmaxf(m, __shfl_xor_sync(0xffffffffu, m, o));
        float sum = 0.f;
        for (int s = tid; s < 80; s += 32) { float e = expf(sc[s] - m); sc[s] = e; sum += e; }
        #pragma unroll
        for (int o = 16; o; o >>= 1) sum += __shfl_xor_sync(0xffffffffu, sum, o);
        float inv = 1.f / sum;
        for (int s = tid; s < 80; s += 32) sc[s] *= inv;
    }
    __syncthreads();
    for (int k = tid; k < 512; k += 256) {
        float a = 0.f;
        #pragma unroll 8
        for (int s = 0; s < 80; s++) a += sc[s] * enc[((size_t)b * 80 + s) * 512 + k];
        g_ctx[b * 512 + k] = a;
    }
}

// ---------------- FFMA2 GEMM micro-kernel (gpre / chain) ------------------------
__device__ __forceinline__ void tile_fma(const float* As, const float* Bs, int tr, int tc,
                                         unsigned long long acc[8][4]) {
    #pragma unroll
    for (int kk = 0; kk < 16; kk++) {
        float4 a0 = *(const float4*)(As + kk * 128 + tr * 4);
        float4 a1 = *(const float4*)(As + kk * 128 + 64 + tr * 4);
        ulonglong2 b0 = *(const ulonglong2*)(Bs + kk * 128 + tc * 4);
        ulonglong2 b1 = *(const ulonglong2*)(Bs + kk * 128 + 64 + tc * 4);
        unsigned long long pb0 = b0.x, pb1 = b0.y, pb2 = b1.x, pb3 = b1.y;
        float av[8] = {a0.x, a0.y, a0.z, a0.w, a1.x, a1.y, a1.z, a1.w};
        #pragma unroll
        for (int i = 0; i < 8; i++) {
            unsigned long long pa = pack2(av[i]);
            ffma2(acc[i][0], pa, pb0);
            ffma2(acc[i][1], pa, pb1);
            ffma2(acc[i][2], pa, pb2);
            ffma2(acc[i][3], pa, pb3);
        }
    }
}
__device__ __forceinline__ void stT(float* S, int r, int lc, float4 v) {
    float* d = S + r;
    d[(lc + 0) * 128] = v.x;
    d[(lc + 1) * 128] = v.y;
    d[(lc + 2) * 128] = v.z;
    d[(lc + 3) * 128] = v.w;
}

// ---------------- Gpre = [emb(tok), ctx] @ W_ih^T + b_ih + b_hh ----------------
__global__ void __launch_bounds__(256, 2) gpre_gemm(
    const int* __restrict__ targets, const float* __restrict__ emb,
    const float* __restrict__ Wih, const float* __restrict__ bih,
    const float* __restrict__ bhh) {
    __shared__ float As[2][16 * 128];
    __shared__ float Bs[2][16 * 128];
    __shared__ int tok[128];
    int t = blockIdx.y;
    int nbase = blockIdx.x * 128;
    int tid = threadIdx.x;
    if (tid < 128) tok[tid] = targets[tid * 28 + t];
    __syncthreads();
    int tr = tid >> 4, tc = tid & 15;
    int lr = tid >> 2, lc = (tid & 3) << 2;
    unsigned long long acc[8][4];
    #pragma unroll
    for (int i = 0; i < 8; i++)
        #pragma unroll
        for (int j = 0; j < 4; j++) acc[i][j] = 0ull;

    float4 ra0, ra1, rb0, rb1;
    ra0 = *(const float4*)(emb + (size_t)tok[lr] * 512 + lc);
    ra1 = *(const float4*)(emb + (size_t)tok[lr + 64] * 512 + lc);
    rb0 = *(const float4*)(Wih + (size_t)(nbase + lr) * 1024 + lc);
    rb1 = *(const float4*)(Wih + (size_t)(nbase + lr + 64) * 1024 + lc);
    stT(As[0], lr, lc, ra0); stT(As[0], lr + 64, lc, ra1);
    stT(Bs[0], lr, lc, rb0); stT(Bs[0], lr + 64, lc, rb1);
    __syncthreads();

    int cur = 0;
    for (int kt = 0; kt < 64; kt++) {
        if (kt < 63) {
            int k0 = (kt + 1) * 16;
            if (k0 < 512) {
                ra0 = *(const float4*)(emb + (size_t)tok[lr] * 512 + k0 + lc);
                ra1 = *(const float4*)(emb + (size_t)tok[lr + 64] * 512 + k0 + lc);
            } else {
                ra0 = *(const float4*)(g_ctx + (size_t)lr * 512 + (k0 - 512) + lc);
                ra1 = *(const float4*)(g_ctx + (size_t)(lr + 64) * 512 + (k0 - 512) + lc);
            }
            rb0 = *(const float4*)(Wih + (size_t)(nbase + lr) * 1024 + k0 + lc);
            rb1 = *(const float4*)(Wih + (size_t)(nbase + lr + 64) * 1024 + k0 + lc);
        }
        tile_fma(As[cur], Bs[cur], tr, tc, acc);
        if (kt < 63) {
            stT(As[cur ^ 1], lr, lc, ra0); stT(As[cur ^ 1], lr + 64, lc, ra1);
            stT(Bs[cur ^ 1], lr, lc, rb0); stT(Bs[cur ^ 1], lr + 64, lc, rb1);
        }
        __syncthreads();
        cur ^= 1;
    }
    #pragma unroll
    for (int i = 0; i < 8; i++) {
        int b = (i < 4) ? tr * 4 + i : 64 + tr * 4 + (i - 4);
        float* dst = g_Gpre + ((size_t)t * 128 + b) * 2048;
        #pragma unroll
        for (int j = 0; j < 4; j++) {
            int nc = nbase + ((j >> 1) << 6) + tc * 4 + ((j & 1) << 1);
            float2 v = unpack2(acc[i][j]);
            dst[nc] = v.x + bih[nc] + bhh[nc];
            dst[nc + 1] = v.y + bih[nc + 1] + bhh[nc + 1];
        }
    }
}

// ---------------- persistent LSTM chain ----------------------------------------
__global__ void __launch_bounds__(256, 1) lstm_chain(const float* __restrict__ elhs,
                                                     const float* __restrict__ Whh) {
    __shared__ float As[2][16 * 128];
    __shared__ float Bs[2][16 * 128];
    int tid = threadIdx.x;
    int nbase = (blockIdx.x & 15) * 128;
    int ks = blockIdx.x >> 4;
    int tr = tid >> 4, tc = tid & 15;
    int lr = tid >> 2, lc = (tid & 3) << 2;
    unsigned epoch = 0;

    for (int t = 0; t < 27; t++) {
        const float* A = (t == 0) ? elhs : (g_H2 + (size_t)(t - 1) * 128 * 512);
        unsigned long long acc[8][4];
        #pragma unroll
        for (int i = 0; i < 8; i++)
            #pragma unroll
            for (int j = 0; j < 4; j++) acc[i][j] = 0ull;

        int kbeg = ks * 64;
        float4 ra0, ra1, rb0, rb1;
        ra0 = *(const float4*)(A + (size_t)lr * 512 + kbeg + lc);
        ra1 = *(const float4*)(A + (size_t)(lr + 64) * 512 + kbeg + lc);
        rb0 = *(const float4*)(Whh + (size_t)(nbase + lr) * 512 + kbeg + lc);
        rb1 = *(const float4*)(Whh + (size_t)(nbase + lr + 64) * 512 + kbeg + lc);
        stT(As[0], lr, lc, ra0); stT(As[0], lr + 64, lc, ra1);
        stT(Bs[0], lr, lc, rb0); stT(Bs[0], lr + 64, lc, rb1);
        __syncthreads();
        int cur = 0;
        #pragma unroll
        for (int kt = 0; kt < 4; kt++) {
            if (kt < 3) {
                int k0 = kbeg + (kt + 1) * 16;
                ra0 = *(const float4*)(A + (size_t)lr * 512 + k0 + lc);
                ra1 = *(const float4*)(A + (size_t)(lr + 64) * 512 + k0 + lc);
                rb0 = *(const float4*)(Whh + (size_t)(nbase + lr) * 512 + k0 + lc);
                rb1 = *(const float4*)(Whh + (size_t)(nbase + lr + 64) * 512 + k0 + lc);
            }
            tile_fma(As[cur], Bs[cur], tr, tc, acc);
            if (kt < 3) {
                stT(As[cur ^ 1], lr, lc, ra0); stT(As[cur ^ 1], lr + 64, lc, ra1);
                stT(Bs[cur ^ 1], lr, lc, rb0); stT(Bs[cur ^ 1], lr + 64, lc, rb1);
            }
            __syncthreads();
            cur ^= 1;
        }
        #pragma unroll
        for (int i = 0; i < 8; i++) {
            int b = (i < 4) ? tr * 4 + i : 64 + tr * 4 + (i - 4);
            float* dst = g_part + ((size_t)ks * 128 + b) * 2048;
            #pragma unroll
            for (int j = 0; j < 4; j++) {
                int nc = nbase + ((j >> 1) << 6) + tc * 4 + ((j & 1) << 1);
                float2 v = unpack2(acc[i][j]);
                dst[nc] = v.x;
                dst[nc + 1] = v.y;
            }
        }
        gsync(++epoch);

        #pragma unroll
        for (int e = 0; e < 2; e++) {
            int idx = e * 32768 + blockIdx.x * 256 + tid;
            int b = idx >> 9, j = idx & 511;
            const float* gp = g_Gpre + ((size_t)t * 128 + b) * 2048;
            float gi = gp[j], gf = gp[j + 512], gg = gp[j + 1024], go = gp[j + 1536];
            #pragma unroll
            for (int kk = 0; kk < 8; kk++) {
                const float* pp = g_part + ((size_t)kk * 128 + b) * 2048;
                gi += __ldcg(pp + j);
                gf += __ldcg(pp + j + 512);
                gg += __ldcg(pp + j + 1024);
                go += __ldcg(pp + j + 1536);
            }
            float cprev = (t == 0) ? 0.f : __ldcg(&g_c[(t - 1) & 1][b * 512 + j]);
            float si = 1.f / (1.f + expf(-gi));
            float sf = 1.f / (1.f + expf(-gf));
            float so = 1.f / (1.f + expf(-go));
            float c2 = sf * cprev + si * tanhf(gg);
            float h2 = so * tanhf(c2);
            g_c[t & 1][b * 512 + j] = c2;
            g_H2[(size_t)t * 128 * 512 + b * 512 + j] = h2;
        }
        gsync(++epoch);
    }
}

// ---------------- fp32 -> (hi, lo) bf16 split -----------------------------------
__global__ void split_kernel(const float* __restrict__ src, __nv_bfloat16* __restrict__ hi,
                             __nv_bfloat16* __restrict__ lo, int n_src) {
    int i0 = (blockIdx.x * 256 + threadIdx.x) * 4;
    #pragma unroll
    for (int u = 0; u < 4; u++) {
        int i = i0 + u;
        float x = (i < n_src) ? src[i] : 0.f;
        __nv_bfloat16 h = __float2bfloat16_rn(x);
        __nv_bfloat16 l = __float2bfloat16_rn(x - __bfloat162float(h));
        hi[i] = h;
        lo[i] = l;
    }
}

// ---------------- HMMA logits GEMM: D(128x128) = A(128x512) @ B(128x512)^T ------
// 3xBF16 split, mma.sync m16n8k16, ldmatrix-native smem tiles, 2-stage cp.async.
// smem tile layout: per 128x16 tile, 32 packed 8x8 bf16 matrices (128B each):
//   mat(rb, kb) at offset (rb*2 + kb)*128; element (row8, col8x2) canonical.
__global__ void __launch_bounds__(256, 1) hmma_logits(const float* __restrict__ bout,
                                                      float* __restrict__ out) {
    __shared__ __align__(128) char smem[2][4][4096];  // [stage][Ahi,Alo,Bhi,Blo]
    int tid = threadIdx.x;
    int lane = tid & 31, wid = tid >> 5;
    int wm = wid & 1, wn = wid >> 1;           // warp grid 2(M) x 4(N)
    int ntile = blockIdx.x, mtile = blockIdx.y;
    int mbase = mtile * 128, nbase = ntile * 128;

    const __nv_bfloat16* gAh = g_Ahi + (size_t)mbase * 512;
    const __nv_bfloat16* gAl = g_Alo + (size_t)mbase * 512;
    const __nv_bfloat16* gBh = g_Whi + (size_t)nbase * 512;
    const __nv_bfloat16* gBl = g_Wlo + (size_t)nbase * 512;

    // loader mapping: thread -> (row r, k-halfblock kb); 16B chunk each
    int r = tid & 127, kb = tid >> 7;
    uint32_t dstoff = (uint32_t)(((r >> 3) * 2 + kb) * 128 + (r & 7) * 16);
    size_t srcoff = (size_t)r * 512 + kb * 8;
    uint32_t s0 = smem_u32(&smem[0][0][0]);
    uint32_t s1 = smem_u32(&smem[1][0][0]);

    // ldmatrix lane offsets
    uint32_t a_lane = (uint32_t)(((((lane >> 3) & 1) * 2 + (lane >> 4)) * 128) + (lane & 7) * 16);
    uint32_t b_lane = (uint32_t)((((lane >> 3) & 3) * 128) + (lane & 7) * 16);

    float d[4][4][4];
    #pragma unroll
    for (int i = 0; i < 4; i++)
        #pragma unroll
        for (int j = 0; j < 4; j++)
            #pragma unroll
            for (int q = 0; q < 4; q++) d[i][j][q] = 0.f;

    // prologue: stage 0 <- k0
    {
        uint32_t db = s0 + dstoff;
        cp16(db,          gAh + srcoff);
        cp16(db + 4096,   gAl + srcoff);
        cp16(db + 8192,   gBh + srcoff);
        cp16(db + 12288,  gBl + srcoff);
        CP_COMMIT();
        CP_WAIT0();
        __syncthreads();
    }

    for (int c = 0; c < 32; c++) {
        uint32_t sb = (c & 1) ? s1 : s0;
        if (c < 31) {
            uint32_t db = ((c & 1) ? s0 : s1) + dstoff;
            size_t so = srcoff + (size_t)(c + 1) * 16;
            cp16(db,         gAh + so);
            cp16(db + 4096,  gAl + so);
            cp16(db + 8192,  gBh + so);
            cp16(db + 12288, gBl + so);
            CP_COMMIT();
        }
        uint32_t ah[4][4], al[4][4], bh[4][2], bl[4][2];
        #pragma unroll
        for (int mt = 0; mt < 4; mt++) {
            ldm_x4(ah[mt], sb + (uint32_t)((wm * 4 + mt) * 512) + a_lane);
            ldm_x4(al[mt], sb + 4096u + (uint32_t)((wm * 4 + mt) * 512) + a_lane);
        }
        #pragma unroll
        for (int p = 0; p < 2; p++) {
            uint32_t rh[4], rl[4];
            ldm_x4(rh, sb + 8192u + (uint32_t)((wn * 4 + 2 * p) * 256) + b_lane);
            ldm_x4(rl, sb + 12288u + (uint32_t)((wn * 4 + 2 * p) * 256) + b_lane);
            bh[2 * p][0] = rh[0]; bh[2 * p][1] = rh[1];
            bh[2 * p + 1][0] = rh[2]; bh[2 * p + 1][1] = rh[3];
            bl[2 * p][0] = rl[0]; bl[2 * p][1] = rl[1];
            bl[2 * p + 1][0] = rl[2]; bl[2 * p + 1][1] = rl[3];
        }
        #pragma unroll
        for (int mt = 0; mt < 4; mt++)
            #pragma unroll
            for (int nt = 0; nt < 4; nt++) {
                mma_bf16(d[mt][nt], ah[mt], bh[nt]);
                mma_bf16(d[mt][nt], ah[mt], bl[nt]);
                mma_bf16(d[mt][nt], al[mt], bh[nt]);
            }
        CP_WAIT0();
        __syncthreads();
    }

    // epilogue: D frag (m16n8): c0,c1 at (row=lane/4, col=2*(lane%4)), c2,c3 at row+8
    #pragma unroll
    for (int nt = 0; nt < 4; nt++) {
        int n = nbase + wn * 32 + nt * 8 + (lane & 3) * 2;
        if (n >= Vv) continue;
        float bx = bout[n], by = bout[n + 1];
        #pragma unroll
        for (int mt = 0; mt < 4; mt++) {
            int m0 = wm * 64 + mt * 16 + (lane >> 2);
            size_t row0 = (size_t)(m0 * 27 + mtile) * Vv;
            size_t row8 = (size_t)((m0 + 8) * 27 + mtile) * Vv;
            float2 v0 = make_float2(d[mt][nt][0] + bx, d[mt][nt][1] + by);
            float2 v1 = make_float2(d[mt][nt][2] + bx, d[mt][nt][3] + by);
            *(float2*)(out + row0 + n) = v0;
            *(float2*)(out + row8 + n) = v1;
        }
    }
}

// ---------------- argmax with exact-fp32 recheck --------------------------------
__global__ void argmax_exact(const float* __restrict__ logits, float* __restrict__ preds,
                             const float* __restrict__ Wout, const float* __restrict__ bout) {
    __shared__ float sv[256];
    __shared__ float hrow[512];
    __shared__ int scand[64];
    __shared__ int ncand;
    __shared__ float bestv;
    __shared__ int besti;
    int rrow = blockIdx.x;
    int tid = threadIdx.x;
    int b = rrow / 27, t = rrow % 27;
    const float4* row4 = (const float4*)(logits + (size_t)rrow * Vv);

    // pass 1: approximate max
    float m = -3.4e38f;
    for (int q = tid; q < Vv / 4; q += 256) {
        float4 v = row4[q];
        m = fmaxf(fmaxf(m, v.x), fmaxf(fmaxf(v.y, v.z), v.w));
    }
    sv[tid] = m;
    __syncthreads();
    for (int o = 128; o; o >>= 1) {
        if (tid < o) sv[tid] = fmaxf(sv[tid], sv[tid + o]);
        __syncthreads();
    }
    float thr = sv[0] - 1e-3f;

    // cache H2 row
    const float* h = g_H2 + ((size_t)t * 128 + b) * 512;
    hrow[tid] = h[tid];
    hrow[tid + 256] = h[tid + 256];
    if (tid == 0) { ncand = 0; bestv = -3.4e38f; besti = 0x7fffffff; }
    __syncthreads();

    // pass 2: collect candidates within threshold of approx max
    for (int q = tid; q < Vv / 4; q += 256) {
        float4 v = row4[q];
        int n = q * 4;
        if (v.x >= thr) { int p = atomicAdd(&ncand, 1); if (p < 64) scand[p] = n; }
        if (v.y >= thr) { int p = atomicAdd(&ncand, 1); if (p < 64) scand[p] = n + 1; }
        if (v.z >= thr) { int p = atomicAdd(&ncand, 1); if (p < 64) scand[p] = n + 2; }
        if (v.w >= thr) { int p = atomicAdd(&ncand, 1); if (p < 64) scand[p] = n + 3; }
    }
    __syncthreads();
    int nc = ncand < 64 ? ncand : 64;

    // exact fp32 evaluation; pick (max value, smallest index) — deterministic
    for (int ci = 0; ci < nc; ci++) {
        int idx = scand[ci];
        const float* wr = Wout + (size_t)idx * 512;
        float p = 0.f;
        for (int k = tid; k < 512; k += 256) p += hrow[k] * wr[k];
        sv[tid] = p;
        __syncthreads();
        for (int o = 128; o; o >>= 1) {
            if (tid < o) sv[tid] += sv[tid + o];
            __syncthreads();
        }
        if (tid == 0) {
            float ev = sv[0] + bout[idx];
            if (ev > bestv || (ev == bestv && idx < besti)) { bestv = ev; besti = idx; }
        }
        __syncthreads();
    }
    if (tid == 0) preds[rrow] = (float)besti;
}

// -------------------------------------------------------------------------------
extern "C" void kernel_launch(void* const* d_in, const int* in_sizes, int n_in,
                              void* d_out, int out_size) {
    const float* elhs    = (const float*)d_in[0];
    const float* enc     = (const float*)d_in[1];
    const int*   targets = (const int*)d_in[2];
    const float* emb     = (const float*)d_in[3];
    const float* W1      = (const float*)d_in[4];
    const float* W2      = (const float*)d_in[6];
    const float* W3      = (const float*)d_in[8];
    const float* W4      = (const float*)d_in[10];
    const float* w_att   = (const float*)d_in[12];
    const float* W_ih    = (const float*)d_in[13];
    const float* W_hh    = (const float*)d_in[14];
    const float* b_ih    = (const float*)d_in[15];
    const float* b_hh    = (const float*)d_in[16];
    const float* W_out   = (const float*)d_in[17];
    const float* b_out   = (const float*)d_in[18];
    float* out = (float*)d_out;

    // split W_out to bf16 hi/lo (padded to VPAD rows; pad region zeroed)
    {
        __nv_bfloat16 *whi, *wlo;
        cudaGetSymbolAddress((void**)&whi, g_Whi);
        cudaGetSymbolAddress((void**)&wlo, g_Wlo);
        split_kernel<<<(VPAD * 512) / 1024, 256>>>(W_out, whi, wlo, Vv * 512);
    }

    mv_kernel<<<8, 256>>>(W4, 512, w_att, 0, 1);
    mv_kernel<<<8, 256>>>(W3, 512, nullptr, 1, 2);
    mv_kernel<<<8, 256>>>(W2, 512, nullptr, 2, 1);
    mv_kernel<<<8, 256>>>(W1, 1024, nullptr, 1, 3);

    attention_kernel<<<128, 256>>>(enc);

    gpre_gemm<<<dim3(16, 27), 256>>>(targets, emb, W_ih, b_ih, b_hh);

    bar_init_kernel<<<1, 1>>>();
    lstm_chain<<<NBLK_CHAIN, 256>>>(elhs, W_hh);

    // split H2 to bf16 hi/lo
    {
        __nv_bfloat16 *ahi, *alo;
        float* h2;
        cudaGetSymbolAddress((void**)&ahi, g_Ahi);
        cudaGetSymbolAddress((void**)&alo, g_Alo);
        cudaGetSymbolAddress((void**)&h2, g_H2);
        split_kernel<<<(3456 * 512) / 1024, 256>>>(h2, ahi, alo, 3456 * 512);
    }

    hmma_logits<<<dim3(235, 27), 256>>>(b_out, out);

    long long main_sz = (long long)3456 * Vv;
    if ((long long)out_size > main_sz)
        argmax_exact<<<3456, 256>>>(out, out + main_sz, W_out, b_out);
}